// round 8
// baseline (speedup 1.0000x reference)
#include <cuda_runtime.h>
#include <cuda_bf16.h>
#include <math.h>

#define N_NODES 100000
#define N_EDGES 1600000
#define F_IN   128
#define H1     200
#define H2     50
#define C_OUT  10
#define MAXDEG 128

// ---------------- scratch -----------------------------------------------------
__device__ int   g_cnt[N_NODES];
__device__ int   g_bucket[(size_t)N_NODES * MAXDEG];
__device__ __nv_bfloat16 g_xh  [(size_t)N_NODES * F_IN];
__device__ __nv_bfloat16 g_xl  [(size_t)N_NODES * F_IN];
__device__ __nv_bfloat16 g_a1h [(size_t)N_NODES * F_IN];
__device__ __nv_bfloat16 g_a1l [(size_t)N_NODES * F_IN];
__device__ float         g_h1f [(size_t)N_NODES * H1];
__device__ __nv_bfloat16 g_h1h [(size_t)N_NODES * H1];
__device__ __nv_bfloat16 g_h1l [(size_t)N_NODES * H1];
__device__ __nv_bfloat16 g_a2h [(size_t)N_NODES * H1];
__device__ __nv_bfloat16 g_a2l [(size_t)N_NODES * H1];
__device__ float g_h2  [(size_t)N_NODES * H2];
__device__ float g_agg3[(size_t)N_NODES * H2];

__device__ __forceinline__ void bf16_split(float x, __nv_bfloat16& h,
                                           __nv_bfloat16& l) {
    h = __float2bfloat16(x);
    l = __float2bfloat16(x - __bfloat162float(h));
}

__device__ __forceinline__ unsigned pack2(__nv_bfloat16 a, __nv_bfloat16 b) {
    __nv_bfloat162 p = __halves2bfloat162(a, b);
    return *reinterpret_cast<unsigned*>(&p);
}

// ---------------- bucket build ------------------------------------------------
__global__ void zero_cnt_kernel() {
    int i = blockIdx.x * blockDim.x + threadIdx.x;
    if (i < N_NODES) g_cnt[i] = 0;
}

__global__ void bucket_build_kernel(const int* __restrict__ src,
                                    const int* __restrict__ dst) {
    int e = blockIdx.x * blockDim.x + threadIdx.x;
    if (e >= N_EDGES) return;
    int d = dst[e];
    int p = atomicAdd(&g_cnt[d], 1);
    if (p < MAXDEG) g_bucket[(size_t)d * MAXDEG + p] = src[e];
}

// ---------------- one-time split of x ----------------------------------------
__global__ void split_x_kernel(const float* __restrict__ x,
                               __nv_bfloat16* __restrict__ xh,
                               __nv_bfloat16* __restrict__ xl) {
    int i = blockIdx.x * blockDim.x + threadIdx.x;
    if (i >= N_NODES * F_IN / 4) return;
    float4 v = ((const float4*)x)[i];
    __nv_bfloat16 h[4], l[4];
    bf16_split(v.x, h[0], l[0]);
    bf16_split(v.y, h[1], l[1]);
    bf16_split(v.z, h[2], l[2]);
    bf16_split(v.w, h[3], l[3]);
    uint2 uh, ul;
    uh.x = pack2(h[0], h[1]); uh.y = pack2(h[2], h[3]);
    ul.x = pack2(l[0], l[1]); ul.y = pack2(l[2], l[3]);
    *(uint2*)(xh + (size_t)i * 4) = uh;
    *(uint2*)(xl + (size_t)i * 4) = ul;
}

__device__ __forceinline__ void fmax4(float4& m, float4 v) {
    m.x = fmaxf(m.x, v.x);
    m.y = fmaxf(m.y, v.y);
    m.z = fmaxf(m.z, v.z);
    m.w = fmaxf(m.w, v.w);
}

// ---------------- aggregation: fp32 gather, MLP=8, split-bf16 output ---------
template <int F>
__global__ void agg_split_kernel(const float* __restrict__ x,
                                 __nv_bfloat16* __restrict__ oh,
                                 __nv_bfloat16* __restrict__ ol) {
    constexpr int C4 = F / 4;               // float4 chunks per row
    constexpr int RV = (C4 + 31) / 32;

    int gwarp = (blockIdx.x * blockDim.x + threadIdx.x) >> 5;
    int lane  = threadIdx.x & 31;
    if (gwarp >= N_NODES) return;

    int c = g_cnt[gwarp];
    if (c > MAXDEG) c = MAXDEG;

    float4 m[RV];
#pragma unroll
    for (int r = 0; r < RV; r++)
        m[r] = make_float4(-INFINITY, -INFINITY, -INFINITY, -INFINITY);

    const int* bk = g_bucket + (size_t)gwarp * MAXDEG;
    int i = 0;
    for (; i + 7 < c; i += 8) {
        int4 sa = *(const int4*)(bk + i);       // broadcast
        int4 sb = *(const int4*)(bk + i + 4);
        const float* p0 = x + (size_t)sa.x * F;
        const float* p1 = x + (size_t)sa.y * F;
        const float* p2 = x + (size_t)sa.z * F;
        const float* p3 = x + (size_t)sa.w * F;
        const float* p4 = x + (size_t)sb.x * F;
        const float* p5 = x + (size_t)sb.y * F;
        const float* p6 = x + (size_t)sb.z * F;
        const float* p7 = x + (size_t)sb.w * F;
#pragma unroll
        for (int r = 0; r < RV; r++) {
            int ch = lane + r * 32;
            if (ch < C4) {
                float4 v0 = ((const float4*)p0)[ch];
                float4 v1 = ((const float4*)p1)[ch];
                float4 v2 = ((const float4*)p2)[ch];
                float4 v3 = ((const float4*)p3)[ch];
                float4 v4 = ((const float4*)p4)[ch];
                float4 v5 = ((const float4*)p5)[ch];
                float4 v6 = ((const float4*)p6)[ch];
                float4 v7 = ((const float4*)p7)[ch];
                fmax4(v0, v1); fmax4(v2, v3); fmax4(v4, v5); fmax4(v6, v7);
                fmax4(v0, v2); fmax4(v4, v6);
                fmax4(v0, v4);
                fmax4(m[r], v0);
            }
        }
    }
    for (; i + 3 < c; i += 4) {
        int4 sa = *(const int4*)(bk + i);
        const float* p0 = x + (size_t)sa.x * F;
        const float* p1 = x + (size_t)sa.y * F;
        const float* p2 = x + (size_t)sa.z * F;
        const float* p3 = x + (size_t)sa.w * F;
#pragma unroll
        for (int r = 0; r < RV; r++) {
            int ch = lane + r * 32;
            if (ch < C4) {
                float4 v0 = ((const float4*)p0)[ch];
                float4 v1 = ((const float4*)p1)[ch];
                float4 v2 = ((const float4*)p2)[ch];
                float4 v3 = ((const float4*)p3)[ch];
                fmax4(v0, v1); fmax4(v2, v3);
                fmax4(v0, v2);
                fmax4(m[r], v0);
            }
        }
    }
    for (; i < c; i++) {
        const float4* p0 = (const float4*)(x + (size_t)bk[i] * F);
#pragma unroll
        for (int r = 0; r < RV; r++) {
            int ch = lane + r * 32;
            if (ch < C4) fmax4(m[r], p0[ch]);
        }
    }

#pragma unroll
    for (int r = 0; r < RV; r++) {
        int ch = lane + r * 32;
        if (ch < C4) {
            float v[4] = {m[r].x, m[r].y, m[r].z, m[r].w};
            __nv_bfloat16 hh[4], ll[4];
#pragma unroll
            for (int q = 0; q < 4; q++) {
                float vv = (c == 0) ? 0.f : v[q];
                bf16_split(vv, hh[q], ll[q]);
            }
            uint2 uh, ul;
            uh.x = pack2(hh[0], hh[1]); uh.y = pack2(hh[2], hh[3]);
            ul.x = pack2(ll[0], ll[1]); ul.y = pack2(ll[2], ll[3]);
            *(uint2*)(oh + (size_t)gwarp * F + ch * 4) = uh;
            *(uint2*)(ol + (size_t)gwarp * F + ch * 4) = ul;
        }
    }
}

// ---------------- fp32 aggregation (layer 3, H2=50), MLP=8 -------------------
__device__ __forceinline__ void fmax2(float2& m, float2 v) {
    m.x = fmaxf(m.x, v.x);
    m.y = fmaxf(m.y, v.y);
}

template <int F>
__global__ void agg_kernel(const float* __restrict__ x, float* __restrict__ agg) {
    constexpr int C2 = F / 2;
    constexpr int RV = (C2 + 31) / 32;

    int gwarp = (blockIdx.x * blockDim.x + threadIdx.x) >> 5;
    int lane  = threadIdx.x & 31;
    if (gwarp >= N_NODES) return;

    int c = g_cnt[gwarp];
    if (c > MAXDEG) c = MAXDEG;

    float2 m[RV];
#pragma unroll
    for (int r = 0; r < RV; r++) { m[r].x = -INFINITY; m[r].y = -INFINITY; }

    const int* bk = g_bucket + (size_t)gwarp * MAXDEG;
    int i = 0;
    for (; i + 7 < c; i += 8) {
        int4 sa = *(const int4*)(bk + i);
        int4 sb = *(const int4*)(bk + i + 4);
        const float2* p0 = (const float2*)(x + (size_t)sa.x * F);
        const float2* p1 = (const float2*)(x + (size_t)sa.y * F);
        const float2* p2 = (const float2*)(x + (size_t)sa.z * F);
        const float2* p3 = (const float2*)(x + (size_t)sa.w * F);
        const float2* p4 = (const float2*)(x + (size_t)sb.x * F);
        const float2* p5 = (const float2*)(x + (size_t)sb.y * F);
        const float2* p6 = (const float2*)(x + (size_t)sb.z * F);
        const float2* p7 = (const float2*)(x + (size_t)sb.w * F);
#pragma unroll
        for (int r = 0; r < RV; r++) {
            int ch = lane + r * 32;
            if (ch < C2) {
                float2 v0 = p0[ch], v1 = p1[ch], v2 = p2[ch], v3 = p3[ch];
                float2 v4 = p4[ch], v5 = p5[ch], v6 = p6[ch], v7 = p7[ch];
                fmax2(v0, v1); fmax2(v2, v3); fmax2(v4, v5); fmax2(v6, v7);
                fmax2(v0, v2); fmax2(v4, v6);
                fmax2(v0, v4);
                fmax2(m[r], v0);
            }
        }
    }
    for (; i + 3 < c; i += 4) {
        int4 sa = *(const int4*)(bk + i);
        const float2* p0 = (const float2*)(x + (size_t)sa.x * F);
        const float2* p1 = (const float2*)(x + (size_t)sa.y * F);
        const float2* p2 = (const float2*)(x + (size_t)sa.z * F);
        const float2* p3 = (const float2*)(x + (size_t)sa.w * F);
#pragma unroll
        for (int r = 0; r < RV; r++) {
            int ch = lane + r * 32;
            if (ch < C2) {
                float2 v0 = p0[ch], v1 = p1[ch], v2 = p2[ch], v3 = p3[ch];
                fmax2(v0, v1); fmax2(v2, v3);
                fmax2(v0, v2);
                fmax2(m[r], v0);
            }
        }
    }
    for (; i < c; i++) {
        const float2* p0 = (const float2*)(x + (size_t)bk[i] * F);
#pragma unroll
        for (int r = 0; r < RV; r++) {
            int ch = lane + r * 32;
            if (ch < C2) fmax2(m[r], p0[ch]);
        }
    }

    float2* out = (float2*)(agg + (size_t)gwarp * F);
#pragma unroll
    for (int r = 0; r < RV; r++) {
        int ch = lane + r * 32;
        if (ch < C2) out[ch] = (c == 0) ? make_float2(0.f, 0.f) : m[r];
    }
}

// ---------------- pre-split bf16 tensor-core dual GEMM -----------------------
#define MMA16816(d, a, b0, b1)                                                \
    asm volatile(                                                             \
        "mma.sync.aligned.m16n8k16.row.col.f32.bf16.bf16.f32 "                \
        "{%0,%1,%2,%3}, {%4,%5,%6,%7}, {%8,%9}, {%0,%1,%2,%3};"               \
        : "+f"(d[0]), "+f"(d[1]), "+f"(d[2]), "+f"(d[3])                      \
        : "r"(a[0]), "r"(a[1]), "r"(a[2]), "r"(a[3]), "r"(b0), "r"(b1))

template <int WN, int NT, int LOGBN, bool SPLIT_OUT>
__global__ __launch_bounds__(256, 2)
void gemm_mma_ps(const __nv_bfloat16* __restrict__ Ah1,
                 const __nv_bfloat16* __restrict__ Al1,
                 const __nv_bfloat16* __restrict__ Ah2,
                 const __nv_bfloat16* __restrict__ Al2,
                 const float* __restrict__ W1, const float* __restrict__ W2,
                 const float* __restrict__ bias,
                 float* __restrict__ outf,
                 __nv_bfloat16* __restrict__ outh,
                 __nv_bfloat16* __restrict__ outl,
                 int M, int K, int NN) {
    constexpr int WM = 4;
    constexpr int BM = 128;
    constexpr int BN = WN * NT * 8;
    constexpr int LDSTR = 24;
    constexpr int BU = (4 * BN) / 256;

    __shared__ __align__(16) __nv_bfloat16 Ash[2][BM * LDSTR];
    __shared__ __align__(16) __nv_bfloat16 Asl[2][BM * LDSTR];
    __shared__ __align__(16) __nv_bfloat16 Bsh[2][BN * LDSTR];
    __shared__ __align__(16) __nv_bfloat16 Bsl[2][BN * LDSTR];

    int tid = threadIdx.x;
    int lane = tid & 31;
    int wid = tid >> 5;
    int wm = wid % WM;
    int wn = wid / WM;
    int g  = lane >> 2;
    int tg = lane & 3;

    int rowBase = blockIdx.y * BM;
    int colBase = blockIdx.x * BN;

    int npt  = (K + 15) >> 4;
    int totT = 2 * npt;

    const int r_  = tid >> 1;
    const int kh_ = (tid & 1) * 8;
    const int aRow = rowBase + r_;

    float acc[2][NT][4];
#pragma unroll
    for (int mt = 0; mt < 2; mt++)
#pragma unroll
        for (int nt = 0; nt < NT; nt++)
#pragma unroll
            for (int q = 0; q < 4; q++) acc[mt][nt][q] = 0.f;

    uint4 pAh, pAl;
    float pB[BU][4];

    auto prefetch = [&](int t) {
        const __nv_bfloat16 *Ah, *Al; const float* W; int ko;
        if (t < npt) { Ah = Ah1; Al = Al1; W = W1; ko = t << 4; }
        else         { Ah = Ah2; Al = Al2; W = W2; ko = (t - npt) << 4; }

        int gk = ko + kh_;
        pAh = make_uint4(0u, 0u, 0u, 0u);
        pAl = make_uint4(0u, 0u, 0u, 0u);
        if (aRow < M && gk + 8 <= K) {
            pAh = *(const uint4*)(Ah + (size_t)aRow * K + gk);
            pAl = *(const uint4*)(Al + (size_t)aRow * K + gk);
        }
#pragma unroll
        for (int bu = 0; bu < BU; bu++) {
            int u = tid + bu * 256;
            int n = u & (BN - 1);
            int kq = (u >> LOGBN) << 2;
            int gn = colBase + n;
#pragma unroll
            for (int q = 0; q < 4; q++) {
                int gk2 = ko + kq + q;
                pB[bu][q] = (gn < NN && gk2 < K) ? W[(size_t)gk2 * NN + gn] : 0.f;
            }
        }
    };

    auto sts = [&](int buf) {
        *(uint4*)&Ash[buf][r_ * LDSTR + kh_] = pAh;
        *(uint4*)&Asl[buf][r_ * LDSTR + kh_] = pAl;
#pragma unroll
        for (int bu = 0; bu < BU; bu++) {
            int u = tid + bu * 256;
            int n = u & (BN - 1);
            int kq = (u >> LOGBN) << 2;
            __nv_bfloat16 h[4], l[4];
#pragma unroll
            for (int q = 0; q < 4; q++) bf16_split(pB[bu][q], h[q], l[q]);
            uint2 uh, ul;
            uh.x = pack2(h[0], h[1]); uh.y = pack2(h[2], h[3]);
            ul.x = pack2(l[0], l[1]); ul.y = pack2(l[2], l[3]);
            *(uint2*)&Bsh[buf][n * LDSTR + kq] = uh;
            *(uint2*)&Bsl[buf][n * LDSTR + kq] = ul;
        }
    };

    auto compute = [&](int buf) {
        unsigned afh[2][4], afl[2][4];
#pragma unroll
        for (int mt = 0; mt < 2; mt++) {
            int r0 = wm * 32 + mt * 16 + g;
            afh[mt][0] = *(const unsigned*)&Ash[buf][(r0)     * LDSTR + 2 * tg];
            afh[mt][1] = *(const unsigned*)&Ash[buf][(r0 + 8) * LDSTR + 2 * tg];
            afh[mt][2] = *(const unsigned*)&Ash[buf][(r0)     * LDSTR + 2 * tg + 8];
            afh[mt][3] = *(const unsigned*)&Ash[buf][(r0 + 8) * LDSTR + 2 * tg + 8];
            afl[mt][0] = *(const unsigned*)&Asl[buf][(r0)     * LDSTR + 2 * tg];
            afl[mt][1] = *(const unsigned*)&Asl[buf][(r0 + 8) * LDSTR + 2 * tg];
            afl[mt][2] = *(const unsigned*)&Asl[buf][(r0)     * LDSTR + 2 * tg + 8];
            afl[mt][3] = *(const unsigned*)&Asl[buf][(r0 + 8) * LDSTR + 2 * tg + 8];
        }
#pragma unroll
        for (int nt = 0; nt < NT; nt++) {
            int c0 = (wn * NT + nt) * 8 + g;
            unsigned bh0 = *(const unsigned*)&Bsh[buf][c0 * LDSTR + 2 * tg];
            unsigned bh1 = *(const unsigned*)&Bsh[buf][c0 * LDSTR + 2 * tg + 8];
            unsigned bl0 = *(const unsigned*)&Bsl[buf][c0 * LDSTR + 2 * tg];
            unsigned bl1 = *(const unsigned*)&Bsl[buf][c0 * LDSTR + 2 * tg + 8];
#pragma unroll
            for (int mt = 0; mt < 2; mt++) {
                MMA16816(acc[mt][nt], afh[mt], bh0, bh1);
                MMA16816(acc[mt][nt], afh[mt], bl0, bl1);
                MMA16816(acc[mt][nt], afl[mt], bh0, bh1);
            }
        }
    };

    prefetch(0);
    sts(0);
    __syncthreads();

    for (int t = 0; t < totT; t++) {
        int buf = t & 1;
        if (t + 1 < totT) prefetch(t + 1);
        compute(buf);
        if (t + 1 < totT) sts(buf ^ 1);
        __syncthreads();
    }

#pragma unroll
    for (int mt = 0; mt < 2; mt++) {
#pragma unroll
        for (int nt = 0; nt < NT; nt++) {
            int col = colBase + (wn * NT + nt) * 8 + 2 * tg;
            if (col >= NN) continue;
            float2 bv = *(const float2*)(bias + col);
            int row0 = rowBase + wm * 32 + mt * 16 + g;
            int row1 = row0 + 8;
            float v0x = acc[mt][nt][0] + bv.x, v0y = acc[mt][nt][1] + bv.y;
            float v1x = acc[mt][nt][2] + bv.x, v1y = acc[mt][nt][3] + bv.y;
            if (row0 < M) {
                if (SPLIT_OUT) {
                    __nv_bfloat16 hx, lx, hy, ly;
                    bf16_split(v0x, hx, lx); bf16_split(v0y, hy, ly);
                    *(unsigned*)(outh + (size_t)row0 * NN + col) = pack2(hx, hy);
                    *(unsigned*)(outl + (size_t)row0 * NN + col) = pack2(lx, ly);
                }
                *(float2*)(outf + (size_t)row0 * NN + col) = make_float2(v0x, v0y);
            }
            if (row1 < M) {
                if (SPLIT_OUT) {
                    __nv_bfloat16 hx, lx, hy, ly;
                    bf16_split(v1x, hx, lx); bf16_split(v1y, hy, ly);
                    *(unsigned*)(outh + (size_t)row1 * NN + col) = pack2(hx, hy);
                    *(unsigned*)(outl + (size_t)row1 * NN + col) = pack2(lx, ly);
                }
                *(float2*)(outf + (size_t)row1 * NN + col) = make_float2(v1x, v1y);
            }
        }
    }
}

// ---------------- final layer + log_softmax ----------------------------------
__global__ void final_kernel(const float* __restrict__ agg,
                             const float* __restrict__ h,
                             const float* __restrict__ Wl,
                             const float* __restrict__ Wr,
                             const float* __restrict__ b,
                             float* __restrict__ out) {
    __shared__ float sWl[H2 * C_OUT], sWr[H2 * C_OUT], sb[C_OUT];
    for (int i = threadIdx.x; i < H2 * C_OUT; i += blockDim.x) {
        sWl[i] = Wl[i];
        sWr[i] = Wr[i];
    }
    if (threadIdx.x < C_OUT) sb[threadIdx.x] = b[threadIdx.x];
    __syncthreads();

    int n = blockIdx.x * blockDim.x + threadIdx.x;
    if (n >= N_NODES) return;

    float logit[C_OUT];
#pragma unroll
    for (int j = 0; j < C_OUT; j++) logit[j] = sb[j];

    const float* ar = agg + (size_t)n * H2;
    const float* hr = h   + (size_t)n * H2;
#pragma unroll 5
    for (int k = 0; k < H2; k++) {
        float a  = ar[k];
        float hh = hr[k];
#pragma unroll
        for (int j = 0; j < C_OUT; j++)
            logit[j] += a * sWl[k * C_OUT + j] + hh * sWr[k * C_OUT + j];
    }

    float mx = logit[0];
#pragma unroll
    for (int j = 1; j < C_OUT; j++) mx = fmaxf(mx, logit[j]);
    float s = 0.0f;
#pragma unroll
    for (int j = 0; j < C_OUT; j++) s += expf(logit[j] - mx);
    float lse = mx + logf(s);
#pragma unroll
    for (int j = 0; j < C_OUT; j++) out[(size_t)n * C_OUT + j] = logit[j] - lse;
}

// ---------------- launch ------------------------------------------------------
extern "C" void kernel_launch(void* const* d_in, const int* in_sizes, int n_in,
                              void* d_out, int out_size) {
    const float* x    = (const float*)d_in[0];
    const int*   ei   = (const int*)d_in[1];
    const float* W_l1 = (const float*)d_in[2];
    const float* b1   = (const float*)d_in[3];
    const float* W_r1 = (const float*)d_in[4];
    const float* W_l2 = (const float*)d_in[5];
    const float* b2   = (const float*)d_in[6];
    const float* W_r2 = (const float*)d_in[7];
    const float* W_l3 = (const float*)d_in[8];
    const float* b3   = (const float*)d_in[9];
    const float* W_r3 = (const float*)d_in[10];
    float* out = (float*)d_out;

    const int* src = ei;
    const int* dst = ei + N_EDGES;

    __nv_bfloat16 *xh, *xl, *a1h, *a1l, *h1h, *h1l, *a2h, *a2l;
    float *h1f, *h2, *agg3;
    cudaGetSymbolAddress((void**)&xh,  g_xh);
    cudaGetSymbolAddress((void**)&xl,  g_xl);
    cudaGetSymbolAddress((void**)&a1h, g_a1h);
    cudaGetSymbolAddress((void**)&a1l, g_a1l);
    cudaGetSymbolAddress((void**)&h1f, g_h1f);
    cudaGetSymbolAddress((void**)&h1h, g_h1h);
    cudaGetSymbolAddress((void**)&h1l, g_h1l);
    cudaGetSymbolAddress((void**)&a2h, g_a2h);
    cudaGetSymbolAddress((void**)&a2l, g_a2l);
    cudaGetSymbolAddress((void**)&h2,  g_h2);
    cudaGetSymbolAddress((void**)&agg3, g_agg3);

    zero_cnt_kernel<<<(N_NODES + 255) / 256, 256>>>();
    bucket_build_kernel<<<(N_EDGES + 255) / 256, 256>>>(src, dst);
    split_x_kernel<<<(N_NODES * F_IN / 4 + 255) / 256, 256>>>(x, xh, xl);

    const int aggBlocks = (N_NODES * 32 + 255) / 256;

    // layer 1
    agg_split_kernel<F_IN><<<aggBlocks, 256>>>(x, a1h, a1l);
    {
        dim3 grid((H1 + 127) / 128, (N_NODES + 127) / 128);
        gemm_mma_ps<2, 8, 7, true><<<grid, 256>>>(
            a1h, a1l, xh, xl, W_l1, W_r1, b1,
            h1f, h1h, h1l, N_NODES, F_IN, H1);
    }

    // layer 2
    agg_split_kernel<H1><<<aggBlocks, 256>>>(h1f, a2h, a2l);
    {
        dim3 grid((H2 + 63) / 64, (N_NODES + 127) / 128);
        gemm_mma_ps<2, 4, 6, false><<<grid, 256>>>(
            a2h, a2l, h1h, h1l, W_l2, W_r2, b2,
            h2, nullptr, nullptr, N_NODES, H1, H2);
    }

    // layer 3 + log_softmax
    agg_kernel<H2><<<aggBlocks, 256>>>(h2, agg3);
    final_kernel<<<(N_NODES + 255) / 256, 256>>>(agg3, h2, W_l3, W_r3, b3, out);
}